// round 16
// baseline (speedup 1.0000x reference)
#include <cuda_runtime.h>
#include <cuda_bf16.h>

// ActionEncoder: out[b] = tanh(b_t + sum_s W_t[:, s*64 + idx[b,s]])
// Quad layout at proper occupancy: 128-thread blocks, grid 1024.
// Per thread, 4 adjacent samples: ONE 256-bit LDG for all 8 indices +
// one int4 types load (2 LDG vs 4), Tb-broadcast smem lookup,
// ex2/rcp/fma tanh, TWO 256-bit STGs.

#define MAX_N 64
#define THREADS 128

__device__ __forceinline__ float ex2f(float x) {
    float r;
    asm("ex2.approx.f32 %0, %1;" : "=f"(r) : "f"(x));
    return r;
}
__device__ __forceinline__ float rcpf(float x) {
    float r;
    asm("rcp.approx.f32 %0, %1;" : "=f"(r) : "f"(x));
    return r;
}
__device__ __forceinline__ float tanh_from_s(float s) {
    // s = 2*log2e*x ; tanh(x) = 1 - 2/(ex2(s)+1)
    float e = ex2f(s);
    return fmaf(-2.f, rcpf(e + 1.f), 1.f);
}

__device__ __forceinline__ float4 enc(const float4* Ta, const float4* Tb,
                                      int t, int i0, int i1) {
    float4 a = Ta[(t << 6) + i0];          // scaled slot0 + bias
    float4 c = Tb[t ? (1 + i1) : 0];       // scaled slot1; broadcast zero for t=0
    return make_float4(tanh_from_s(a.x + c.x), tanh_from_s(a.y + c.y),
                       tanh_from_s(a.z + c.z), tanh_from_s(a.w + c.w));
}

__device__ __forceinline__ void stg256(float4* dst, float4 r0, float4 r1) {
    asm volatile("st.global.v8.f32 [%0], {%1,%2,%3,%4,%5,%6,%7,%8};"
                 :: "l"((float*)dst),
                    "f"(r0.x), "f"(r0.y), "f"(r0.z), "f"(r0.w),
                    "f"(r1.x), "f"(r1.y), "f"(r1.z), "f"(r1.w)
                 : "memory");
}

__global__ __launch_bounds__(THREADS)
void action_encoder_kernel(const float* __restrict__ idxf,   // [2B] indices (bit-cast loads)
                           const int4* __restrict__ types4,  // [B/4] four types
                           const float* __restrict__ W0,     // [4,64]
                           const float* __restrict__ b0,     // [4]
                           const float* __restrict__ W1,     // [4,128]
                           const float* __restrict__ b1,     // [4]
                           float4* __restrict__ out,         // [B]
                           int Bquads) {
    __shared__ float4 Ta[2 * MAX_N];   // [t*64+i0]: 2*log2e*(W slot0 + b)
    __shared__ float4 Tb[1 + MAX_N];   // [0]=0 ; [1+i1]: 2*log2e*(W1 slot1)
    const float S = 2.8853900817779268f;   // 2*log2(e)
    int tid = threadIdx.x;
    if (tid < MAX_N) {
        Ta[tid] = make_float4(S * (W0[0*64 + tid] + b0[0]),
                              S * (W0[1*64 + tid] + b0[1]),
                              S * (W0[2*64 + tid] + b0[2]),
                              S * (W0[3*64 + tid] + b0[3]));
        Tb[1 + tid] = make_float4(S * W1[0*128 + 64 + tid],
                                  S * W1[1*128 + 64 + tid],
                                  S * W1[2*128 + 64 + tid],
                                  S * W1[3*128 + 64 + tid]);
    } else {
        int j = tid - MAX_N;
        Ta[tid] = make_float4(S * (W1[0*128 + j] + b1[0]),
                              S * (W1[1*128 + j] + b1[1]),
                              S * (W1[2*128 + j] + b1[2]),
                              S * (W1[3*128 + j] + b1[3]));
        if (j == 0) Tb[0] = make_float4(0.f, 0.f, 0.f, 0.f);
    }
    __syncthreads();

    int q = blockIdx.x * THREADS + tid;   // quad index (4 adjacent samples)
    if (q >= Bquads) return;

    // One 256-bit load: 8 index ints (bit-cast through f32; moves only, no
    // arithmetic, so denormal ints are preserved exactly).
    float f0, f1, f2, f3, f4, f5, f6, f7;
    asm("ld.global.v8.f32 {%0,%1,%2,%3,%4,%5,%6,%7}, [%8];"
        : "=f"(f0), "=f"(f1), "=f"(f2), "=f"(f3),
          "=f"(f4), "=f"(f5), "=f"(f6), "=f"(f7)
        : "l"(idxf + 8 * (long)q));
    int i00 = __float_as_int(f0), i01 = __float_as_int(f1);
    int i10 = __float_as_int(f2), i11 = __float_as_int(f3);
    int i20 = __float_as_int(f4), i21 = __float_as_int(f5);
    int i30 = __float_as_int(f6), i31 = __float_as_int(f7);

    int4 tt = types4[q];   // one coalesced 16B load: 4 types

    float4 r0 = enc(Ta, Tb, tt.x, i00, i01);
    float4 r1 = enc(Ta, Tb, tt.y, i10, i11);
    float4 r2 = enc(Ta, Tb, tt.z, i20, i21);
    float4 r3 = enc(Ta, Tb, tt.w, i30, i31);

    stg256(out + 4 * q,     r0, r1);
    stg256(out + 4 * q + 2, r2, r3);
}

extern "C" void kernel_launch(void* const* d_in, const int* in_sizes, int n_in,
                              void* d_out, int out_size) {
    // metadata order: action_indecies, action_n_obj, action_types, W0, b0, W1, b1
    const float* idxf   = (const float*)d_in[0];   // bit-cast index loads
    const int4*  types4 = (const int4*) d_in[2];
    const float* W0     = (const float*)d_in[3];
    const float* b0     = (const float*)d_in[4];
    const float* W1     = (const float*)d_in[5];
    const float* b1     = (const float*)d_in[6];
    float4* out = (float4*)d_out;

    int B = in_sizes[2];      // 524288 (divisible by 4)
    int Bquads = B >> 2;      // 131072

    int blocks = (Bquads + THREADS - 1) / THREADS;  // 1024
    action_encoder_kernel<<<blocks, THREADS>>>(idxf, types4, W0, b0, W1, b1,
                                               out, Bquads);
}